// round 4
// baseline (speedup 1.0000x reference)
#include <cuda_runtime.h>
#include <cuda_bf16.h>

// ---------------------------------------------------------------------------
// Transformer block, fp32. All big ops are C = A @ W^T handled by one
// templated SGEMM (128x128x16 tile, 256 thr, 8x8 microtile), batched over
// attention heads via gridDim.z. Epilogues fused: relu+bias, residual add,
// per-(row,head) attention scaling.
// ---------------------------------------------------------------------------

#define T_SEQ   2048
#define C_EMB   4096
#define QKV_OUT 6144            // (32 + 2*8) * 128
#define FFN_DIM 11008
#define NHEAD   32
#define NKV     8
#define HDIM    128

// ------------------------- scratch (static device memory) ------------------
__device__ float g_n1[T_SEQ * C_EMB];
__device__ float g_qkv[T_SEQ * QKV_OUT];
__device__ float g_scaling[T_SEQ * C_EMB];
__device__ float g_scale_t[T_SEQ * NHEAD];
__device__ float g_Qb[(long)NHEAD * T_SEQ * HDIM];
__device__ float g_Kb[(long)NKV * T_SEQ * HDIM];
__device__ float g_scores[(long)NHEAD * T_SEQ * T_SEQ];   // 537 MB
__device__ float g_y[T_SEQ * C_EMB];
__device__ float g_x2[T_SEQ * C_EMB];
__device__ float g_n2[T_SEQ * C_EMB];
__device__ float g_gate[T_SEQ * FFN_DIM];
__device__ float g_up[T_SEQ * FFN_DIM];

// ------------------------------- SGEMM --------------------------------------
// C[m][n] = sum_k A[m*lda+k] * (BKM ? B[n*ldb+k] : B[k*ldb+n])
// Batched: A += z*sA; B += (z/bdiv)*sB; C += z*sC.
// EPI: 0 none, 1 relu(acc+bias[col]), 2 acc+aux[row*ldc+col], 3 acc*alpha*aux[row*32+z]
#define BM 128
#define BN 128
#define BKT 16

template<int EPI, bool BKM>
__launch_bounds__(256, 2)
__global__ void sgemm_kernel(const float* __restrict__ A, const float* __restrict__ B,
                             float* __restrict__ C, int K,
                             int lda, int ldb, int ldc,
                             long sA, long sB, long sC, int bdiv,
                             const float* __restrict__ aux, float alpha)
{
    __shared__ float As[BKT][BM];
    __shared__ float Bs[BKT][BN];

    const int z = blockIdx.z;
    A += (long)z * sA;
    B += (long)(z / bdiv) * sB;
    C += (long)z * sC;

    const int m0 = blockIdx.y * BM;
    const int n0 = blockIdx.x * BN;
    const int tid = threadIdx.x;
    const int tx = tid & 15;
    const int ty = tid >> 4;

    float acc[8][8];
#pragma unroll
    for (int i = 0; i < 8; i++)
#pragma unroll
        for (int j = 0; j < 8; j++) acc[i][j] = 0.f;

    for (int k0 = 0; k0 < K; k0 += BKT) {
        // A tile: 128 rows x 16 k, float4 along k, store transposed
#pragma unroll
        for (int i = 0; i < 2; i++) {
            int idx = tid + i * 256;
            int row = idx >> 2, kq = idx & 3;
            float4 v = *(const float4*)(A + (long)(m0 + row) * lda + k0 + kq * 4);
            As[kq * 4 + 0][row] = v.x;
            As[kq * 4 + 1][row] = v.y;
            As[kq * 4 + 2][row] = v.z;
            As[kq * 4 + 3][row] = v.w;
        }
        if (BKM) {
#pragma unroll
            for (int i = 0; i < 2; i++) {
                int idx = tid + i * 256;
                int row = idx >> 2, kq = idx & 3;   // row = n index
                float4 v = *(const float4*)(B + (long)(n0 + row) * ldb + k0 + kq * 4);
                Bs[kq * 4 + 0][row] = v.x;
                Bs[kq * 4 + 1][row] = v.y;
                Bs[kq * 4 + 2][row] = v.z;
                Bs[kq * 4 + 3][row] = v.w;
            }
        } else {
#pragma unroll
            for (int i = 0; i < 2; i++) {
                int idx = tid + i * 256;
                int kr = idx >> 5, nq = idx & 31;
                float4 v = *(const float4*)(B + (long)(k0 + kr) * ldb + n0 + nq * 4);
                *(float4*)&Bs[kr][nq * 4] = v;
            }
        }
        __syncthreads();

#pragma unroll
        for (int kk = 0; kk < BKT; kk++) {
            float a[8], b[8];
            *(float4*)&a[0] = *(const float4*)&As[kk][ty * 4];
            *(float4*)&a[4] = *(const float4*)&As[kk][64 + ty * 4];
            *(float4*)&b[0] = *(const float4*)&Bs[kk][tx * 4];
            *(float4*)&b[4] = *(const float4*)&Bs[kk][64 + tx * 4];
#pragma unroll
            for (int i = 0; i < 8; i++)
#pragma unroll
                for (int j = 0; j < 8; j++)
                    acc[i][j] += a[i] * b[j];
        }
        __syncthreads();
    }

    // epilogue
#pragma unroll
    for (int i = 0; i < 8; i++) {
        int row = m0 + ((i < 4) ? (ty * 4 + i) : (64 + ty * 4 + i - 4));
        float srow = 1.f;
        if (EPI == 3) srow = alpha * aux[(long)row * 32 + z];
#pragma unroll
        for (int jh = 0; jh < 2; jh++) {
            int col0 = n0 + (jh ? (64 + tx * 4) : (tx * 4));
            float4 v;
            float* pv = (float*)&v;
#pragma unroll
            for (int j = 0; j < 4; j++) {
                float val = acc[i][jh * 4 + j];
                int col = col0 + j;
                if (EPI == 1) { val += aux[col]; val = val > 0.f ? val : 0.f; }
                else if (EPI == 2) { val += aux[(long)row * ldc + col]; }
                else if (EPI == 3) { val *= srow; }
                pv[j] = val;
            }
            *(float4*)(C + (long)row * ldc + col0) = v;
        }
    }
}

// ------------------------------ small kernels --------------------------------

__global__ void rmsnorm_kernel(const float* __restrict__ x,
                               const float* __restrict__ w,
                               float* __restrict__ out)
{
    int t = blockIdx.x;
    const float4* xr = (const float4*)(x + (long)t * C_EMB);
    float s = 0.f;
    for (int i = threadIdx.x; i < C_EMB / 4; i += 256) {
        float4 v = xr[i];
        s += v.x * v.x + v.y * v.y + v.z * v.z + v.w * v.w;
    }
    __shared__ float red[256];
    red[threadIdx.x] = s;
    __syncthreads();
    for (int off = 128; off > 0; off >>= 1) {
        if (threadIdx.x < off) red[threadIdx.x] += red[threadIdx.x + off];
        __syncthreads();
    }
    float inv = rsqrtf(red[0] / (float)C_EMB + 1e-5f);
    float4* o = (float4*)(out + (long)t * C_EMB);
    const float4* wv = (const float4*)w;
    for (int i = threadIdx.x; i < C_EMB / 4; i += 256) {
        float4 v = xr[i];
        float4 ww = wv[i];
        float4 r;
        r.x = v.x * inv * ww.x;
        r.y = v.y * inv * ww.y;
        r.z = v.z * inv * ww.z;
        r.w = v.w * inv * ww.w;
        o[i] = r;
    }
}

// rope for Q heads: gather from qkv into Qb[h][t][d]
__global__ void ropeq_kernel(const float* __restrict__ qkv,
                             const float* __restrict__ cos_,
                             const float* __restrict__ sin_,
                             float* __restrict__ Qb)
{
    long idx = (long)blockIdx.x * 256 + threadIdx.x;   // 32*2048*64
    if (idx >= (long)NHEAD * T_SEQ * 64) return;
    int d = idx & 63;
    int t = (int)((idx >> 6) & (T_SEQ - 1));
    int h = (int)(idx >> 17);
    int g = h >> 2, slot = h & 3;
    const float* base = qkv + (long)t * QKV_OUT + (g * 6 + slot) * HDIM;
    float x1 = base[d], x2 = base[d + 64];
    const float* cr = cos_ + (long)t * HDIM;
    const float* sr = sin_ + (long)t * HDIM;
    float* ob = Qb + ((long)h * T_SEQ + t) * HDIM;
    ob[d]      = x1 * cr[d]      - x2 * sr[d];
    ob[d + 64] = x2 * cr[d + 64] + x1 * sr[d + 64];
}

// rope for K heads: gather from qkv into Kb[g][t][d]
__global__ void ropek_kernel(const float* __restrict__ qkv,
                             const float* __restrict__ cos_,
                             const float* __restrict__ sin_,
                             float* __restrict__ Kb)
{
    long idx = (long)blockIdx.x * 256 + threadIdx.x;   // 8*2048*64
    if (idx >= (long)NKV * T_SEQ * 64) return;
    int d = idx & 63;
    int t = (int)((idx >> 6) & (T_SEQ - 1));
    int g = (int)(idx >> 17);
    const float* base = qkv + (long)t * QKV_OUT + (g * 6 + 4) * HDIM;
    float x1 = base[d], x2 = base[d + 64];
    const float* cr = cos_ + (long)t * HDIM;
    const float* sr = sin_ + (long)t * HDIM;
    float* ob = Kb + ((long)g * T_SEQ + t) * HDIM;
    ob[d]      = x1 * cr[d]      - x2 * sr[d];
    ob[d + 64] = x2 * cr[d + 64] + x1 * sr[d + 64];
}

// per-(token, head) mean of relu'd scaling: scale_t[t*32+h]
__global__ void scalet_kernel(const float* __restrict__ scaling,
                              float* __restrict__ scale_t)
{
    int t = blockIdx.x;
    int w = threadIdx.x >> 5, lane = threadIdx.x & 31;   // 32 warps = 32 heads
    const float* p = scaling + (long)t * C_EMB + w * HDIM;
    float s = p[lane] + p[lane + 32] + p[lane + 64] + p[lane + 96];
    for (int off = 16; off; off >>= 1) s += __shfl_down_sync(0xffffffffu, s, off);
    if (lane == 0) scale_t[t * NHEAD + w] = s * (1.f / 128.f);
}

// row softmax over 2048 elements, in place
__global__ void softmax_kernel(float* __restrict__ scores)
{
    long row = blockIdx.x;
    float* p = scores + row * (long)T_SEQ;
    int tid = threadIdx.x;
    float v[8];
    float m = -1e30f;
#pragma unroll
    for (int i = 0; i < 8; i++) {
        v[i] = p[tid + i * 256];
        m = fmaxf(m, v[i]);
    }
    __shared__ float red[256];
    red[tid] = m;
    __syncthreads();
    for (int off = 128; off; off >>= 1) {
        if (tid < off) red[tid] = fmaxf(red[tid], red[tid + off]);
        __syncthreads();
    }
    m = red[0];
    __syncthreads();
    float s = 0.f;
#pragma unroll
    for (int i = 0; i < 8; i++) {
        v[i] = __expf(v[i] - m);
        s += v[i];
    }
    red[tid] = s;
    __syncthreads();
    for (int off = 128; off; off >>= 1) {
        if (tid < off) red[tid] += red[tid + off];
        __syncthreads();
    }
    float inv = 1.f / red[0];
#pragma unroll
    for (int i = 0; i < 8; i++) p[tid + i * 256] = v[i] * inv;
}

__global__ void silumul_kernel(float* __restrict__ g, const float* __restrict__ u, long n)
{
    long i = (long)blockIdx.x * 256 + threadIdx.x;
    if (i < n) {
        float gv = g[i];
        float uv = u[i];
        g[i] = gv * uv / (1.f + __expf(-gv));
    }
}

// ------------------------------- launch -------------------------------------

extern "C" void kernel_launch(void* const* d_in, const int* in_sizes, int n_in,
                              void* d_out, int out_size)
{
    const float* x       = (const float*)d_in[0];
    const float* cosp    = (const float*)d_in[1];
    const float* sinp    = (const float*)d_in[2];
    const float* norm1_w = (const float*)d_in[3];
    const float* norm2_w = (const float*)d_in[4];
    const float* attn_w  = (const float*)d_in[5];
    const float* proj_w  = (const float*)d_in[6];
    const float* scale_w = (const float*)d_in[7];
    const float* scale_b = (const float*)d_in[8];
    const float* gate_w  = (const float*)d_in[9];
    const float* up_w    = (const float*)d_in[10];
    const float* down_w  = (const float*)d_in[11];
    float* out = (float*)d_out;

    float *n1, *qkv, *scaling, *scale_t, *Qb, *Kb, *scores, *y, *x2, *n2, *gateb, *upb;
    cudaGetSymbolAddress((void**)&n1, g_n1);
    cudaGetSymbolAddress((void**)&qkv, g_qkv);
    cudaGetSymbolAddress((void**)&scaling, g_scaling);
    cudaGetSymbolAddress((void**)&scale_t, g_scale_t);
    cudaGetSymbolAddress((void**)&Qb, g_Qb);
    cudaGetSymbolAddress((void**)&Kb, g_Kb);
    cudaGetSymbolAddress((void**)&scores, g_scores);
    cudaGetSymbolAddress((void**)&y, g_y);
    cudaGetSymbolAddress((void**)&x2, g_x2);
    cudaGetSymbolAddress((void**)&n2, g_n2);
    cudaGetSymbolAddress((void**)&gateb, g_gate);
    cudaGetSymbolAddress((void**)&upb, g_up);

    const float sf = 0.08838834764831843f;   // 1/sqrt(128)

    // 1. n1 = rmsnorm(x, norm1_w)
    rmsnorm_kernel<<<T_SEQ, 256>>>(x, norm1_w, n1);

    // 2. qkv = n1 @ attn_w^T
    {
        dim3 grid(QKV_OUT / BN, T_SEQ / BM);
        sgemm_kernel<0, true><<<grid, 256>>>(n1, attn_w, qkv, C_EMB,
                                             C_EMB, C_EMB, QKV_OUT,
                                             0, 0, 0, 1, nullptr, 0.f);
    }
    // 3. scaling = relu(n1 @ scale_w^T + scale_b)
    {
        dim3 grid(C_EMB / BN, T_SEQ / BM);
        sgemm_kernel<1, true><<<grid, 256>>>(n1, scale_w, scaling, C_EMB,
                                             C_EMB, C_EMB, C_EMB,
                                             0, 0, 0, 1, scale_b, 0.f);
    }
    // 4. scale_t[t][h] = mean_d scaling
    scalet_kernel<<<T_SEQ, 1024>>>(scaling, scale_t);

    // 5. rope + gather Q, K
    ropeq_kernel<<<(NHEAD * T_SEQ * 64) / 256, 256>>>(qkv, cosp, sinp, Qb);
    ropek_kernel<<<(NKV * T_SEQ * 64) / 256, 256>>>(qkv, cosp, sinp, Kb);

    // 6. scores[h] = (Q[h] @ K[g]^T) * sf * scale_t[:,h]
    {
        dim3 grid(T_SEQ / BN, T_SEQ / BM, NHEAD);
        sgemm_kernel<3, true><<<grid, 256>>>(Qb, Kb, scores, HDIM,
                                             HDIM, HDIM, T_SEQ,
                                             (long)T_SEQ * HDIM, (long)T_SEQ * HDIM,
                                             (long)T_SEQ * T_SEQ, 4,
                                             scale_t, sf);
    }
    // 7. softmax rows
    softmax_kernel<<<NHEAD * T_SEQ, 256>>>(scores);

    // 8. y[:, h*128:(h+1)*128] = P[h] @ V[g]   (V read straight from qkv)
    {
        dim3 grid(1, T_SEQ / BM, NHEAD);
        sgemm_kernel<0, false><<<grid, 256>>>(scores, qkv + 5 * HDIM, y, T_SEQ,
                                              T_SEQ, QKV_OUT, C_EMB,
                                              (long)T_SEQ * T_SEQ, (long)6 * HDIM,
                                              (long)HDIM, 4,
                                              nullptr, 0.f);
    }
    // 9. x2 = x + y @ proj_w^T
    {
        dim3 grid(C_EMB / BN, T_SEQ / BM);
        sgemm_kernel<2, true><<<grid, 256>>>(y, proj_w, x2, C_EMB,
                                             C_EMB, C_EMB, C_EMB,
                                             0, 0, 0, 1, x, 0.f);
    }
    // 10. n2 = rmsnorm(x2, norm2_w)
    rmsnorm_kernel<<<T_SEQ, 256>>>(x2, norm2_w, n2);

    // 11/12. gate & up
    {
        dim3 grid(FFN_DIM / BN, T_SEQ / BM);
        sgemm_kernel<0, true><<<grid, 256>>>(n2, gate_w, gateb, C_EMB,
                                             C_EMB, C_EMB, FFN_DIM,
                                             0, 0, 0, 1, nullptr, 0.f);
        sgemm_kernel<0, true><<<grid, 256>>>(n2, up_w, upb, C_EMB,
                                             C_EMB, C_EMB, FFN_DIM,
                                             0, 0, 0, 1, nullptr, 0.f);
    }
    // 13. gate = silu(gate) * up
    {
        long n = (long)T_SEQ * FFN_DIM;
        silumul_kernel<<<(unsigned)((n + 255) / 256), 256>>>(gateb, upb, n);
    }
    // 14. out = x2 + gate @ down_w^T
    {
        dim3 grid(C_EMB / BN, T_SEQ / BM);
        sgemm_kernel<2, true><<<grid, 256>>>(gateb, down_w, out, FFN_DIM,
                                             FFN_DIM, FFN_DIM, C_EMB,
                                             0, 0, 0, 1, x2, 0.f);
    }
}

// round 9
// speedup vs baseline: 2.5936x; 2.5936x over previous
#include <cuda_runtime.h>
#include <cuda_bf16.h>
#include <cstdint>

// ---------------------------------------------------------------------------
// Transformer block via classical tensor-core path (mma.sync bf16, sm_80 PTX,
// compiles at compute_103). All GEMMs: C = A @ B^T, A/B pre-split into bf16
// hi/lo planes; fp32 accum of AhBh + AhBl + AlBh gives fp32-class accuracy.
// 128x128x64 CTA tile, 3-stage cp.async pipeline, swizzled smem + ldmatrix.
// ---------------------------------------------------------------------------

#define T_SEQ   2048
#define C_EMB   4096
#define QKV_OUT 6144
#define FFN_DIM 11008
#define NHEAD   32
#define NKV     8
#define HDIM    128

typedef __nv_bfloat16 bf16;

// ------------------------- scratch (static device memory) ------------------
__device__ float g_qkv[T_SEQ * QKV_OUT];
__device__ float g_scaling[T_SEQ * C_EMB];
__device__ float g_scale_t[T_SEQ * NHEAD];
__device__ float g_scores[(long)NHEAD * T_SEQ * T_SEQ];   // reused as P hi/lo bf16
__device__ float g_x2[T_SEQ * C_EMB];
__device__ float g_gate[(long)T_SEQ * FFN_DIM];
__device__ float g_up[(long)T_SEQ * FFN_DIM];

__device__ bf16 g_n1h[T_SEQ * C_EMB], g_n1l[T_SEQ * C_EMB];
__device__ bf16 g_n2h[T_SEQ * C_EMB], g_n2l[T_SEQ * C_EMB];
__device__ bf16 g_yh[T_SEQ * C_EMB],  g_yl[T_SEQ * C_EMB];
__device__ bf16 g_qh[(long)NHEAD * T_SEQ * HDIM], g_ql[(long)NHEAD * T_SEQ * HDIM];
__device__ bf16 g_kh[(long)NKV * T_SEQ * HDIM],   g_kl[(long)NKV * T_SEQ * HDIM];
__device__ bf16 g_vth[(long)NKV * HDIM * T_SEQ],  g_vtl[(long)NKV * HDIM * T_SEQ];
__device__ bf16 g_gh[(long)T_SEQ * FFN_DIM], g_gl[(long)T_SEQ * FFN_DIM];

__device__ bf16 g_aWh[(long)QKV_OUT * C_EMB], g_aWl[(long)QKV_OUT * C_EMB];
__device__ bf16 g_sWh[(long)C_EMB * C_EMB],   g_sWl[(long)C_EMB * C_EMB];
__device__ bf16 g_pWh[(long)C_EMB * C_EMB],   g_pWl[(long)C_EMB * C_EMB];
__device__ bf16 g_gWh[(long)FFN_DIM * C_EMB], g_gWl[(long)FFN_DIM * C_EMB];
__device__ bf16 g_uWh[(long)FFN_DIM * C_EMB], g_uWl[(long)FFN_DIM * C_EMB];
__device__ bf16 g_dWh[(long)C_EMB * FFN_DIM], g_dWl[(long)C_EMB * FFN_DIM];

// ------------------------------ PTX helpers ---------------------------------
__device__ __forceinline__ uint32_t smem_u32(const void* p) {
    uint32_t a;
    asm("{ .reg .u64 t; cvta.to.shared.u64 t, %1; cvt.u32.u64 %0, t; }" : "=r"(a) : "l"(p));
    return a;
}

__device__ __forceinline__ void cp16(uint32_t dst, const void* src) {
    asm volatile("cp.async.cg.shared.global [%0], [%1], 16;" :: "r"(dst), "l"(src));
}
#define CP_COMMIT() asm volatile("cp.async.commit_group;" ::: "memory")
#define CP_WAIT1()  asm volatile("cp.async.wait_group 1;" ::: "memory")
#define CP_WAIT0()  asm volatile("cp.async.wait_group 0;" ::: "memory")

__device__ __forceinline__ void ldm4(uint32_t (&r)[4], uint32_t addr) {
    asm volatile("ldmatrix.sync.aligned.m8n8.x4.shared.b16 {%0,%1,%2,%3}, [%4];"
        : "=r"(r[0]), "=r"(r[1]), "=r"(r[2]), "=r"(r[3]) : "r"(addr));
}

__device__ __forceinline__ void mma16816(float (&c)[4], const uint32_t (&a)[4],
                                         uint32_t b0, uint32_t b1) {
    asm volatile("mma.sync.aligned.m16n8k16.row.col.f32.bf16.bf16.f32 "
        "{%0,%1,%2,%3}, {%4,%5,%6,%7}, {%8,%9}, {%0,%1,%2,%3};"
        : "+f"(c[0]), "+f"(c[1]), "+f"(c[2]), "+f"(c[3])
        : "r"(a[0]), "r"(a[1]), "r"(a[2]), "r"(a[3]), "r"(b0), "r"(b1));
}

__device__ __forceinline__ void bf16split(float v, bf16& h, bf16& l) {
    h = __float2bfloat16(v);
    l = __float2bfloat16(v - __bfloat162float(h));
}

// ------------------------------ GEMM kernel ---------------------------------
// C[m][n] = sum_k A[m,k]*B[n,k]; tiles 128x128, K step 64.
// Smem stage (64 KB): Ah[128x64] Al Bh Bl, 128B swizzled rows. 3 stages.
// EPI: 0 none, 1 relu(acc+aux[col]), 2 acc+aux[row*ldc+col],
//      3 acc*alpha*aux[row*32+z], 4 bf16-split store to OH/OL.
#define ASZ 16384
#define STG 65536

template<int EPI>
__global__ __launch_bounds__(256, 1)
void tcmm(const bf16* __restrict__ Ah, const bf16* __restrict__ Al,
          const bf16* __restrict__ Bh, const bf16* __restrict__ Bl,
          float* __restrict__ C, bf16* __restrict__ OH, bf16* __restrict__ OL,
          int K, int lda, int ldb, int ldc,
          long sA, long sB, long sC, int bdiv,
          const float* __restrict__ aux, float alpha)
{
    extern __shared__ char sm[];
    const uint32_t sbase = smem_u32(sm);

    const int tid = threadIdx.x, wid = tid >> 5, lane = tid & 31;
    const int wm = wid & 1, wn = wid >> 1;        // 2 x 4 warp grid; warp tile 64x32
    const int half = lane >> 4;
    const int z = blockIdx.z;
    Ah += (long)z * sA;  Al += (long)z * sA;
    { long bo = (long)(z / bdiv) * sB; Bh += bo; Bl += bo; }
    const long m0 = (long)blockIdx.x * 128;
    const long n0 = (long)blockIdx.y * 128;

    // ldmatrix per-thread row offsets
    int aoff[4], asw[4], boff[2], bsw[2];
#pragma unroll
    for (int mi = 0; mi < 4; mi++) {
        int r = wm * 64 + mi * 16 + (lane & 15);
        aoff[mi] = r * 128; asw[mi] = (r & 7) << 4;
    }
#pragma unroll
    for (int nj = 0; nj < 2; nj++) {
        int r = wn * 32 + nj * 16 + (lane & 15);
        boff[nj] = r * 128; bsw[nj] = (r & 7) << 4;
    }

    float acc[4][4][4];
#pragma unroll
    for (int mi = 0; mi < 4; mi++)
#pragma unroll
        for (int ni = 0; ni < 4; ni++)
#pragma unroll
            for (int j = 0; j < 4; j++) acc[mi][ni][j] = 0.f;

    const int niter = K >> 6;

    // loader: row = (tid>>3)+i*32, chunk c = tid&7
    const int lr = tid >> 3, lc = tid & 7;

#define ISSUE(it_) do {                                                         \
    int _s = (it_) % 3;                                                         \
    long _k0 = (long)(it_) << 6;                                                \
    uint32_t _st = sbase + _s * STG;                                            \
    _Pragma("unroll")                                                           \
    for (int i = 0; i < 4; i++) {                                               \
        int row = lr + i * 32;                                                  \
        uint32_t off = row * 128 + (((lc ^ (row & 7))) << 4);                   \
        long ga = (m0 + row) * (long)lda + _k0 + lc * 8;                        \
        long gb = (n0 + row) * (long)ldb + _k0 + lc * 8;                        \
        cp16(_st + off,             Ah + ga);                                   \
        cp16(_st + ASZ + off,       Al + ga);                                   \
        cp16(_st + 2 * ASZ + off,   Bh + gb);                                   \
        cp16(_st + 3 * ASZ + off,   Bl + gb);                                   \
    }                                                                           \
    CP_COMMIT();                                                                \
} while (0)

    ISSUE(0);
    ISSUE(1);

    for (int it = 0; it < niter; ++it) {
        if (it + 1 < niter) CP_WAIT1(); else CP_WAIT0();
        __syncthreads();
        if (it + 2 < niter) ISSUE(it + 2);

        const uint32_t st = sbase + (it % 3) * STG;
#pragma unroll
        for (int ks = 0; ks < 4; ks++) {
            const uint32_t csel = (uint32_t)(((ks << 1) | half) << 4);
            uint32_t aHf[4][4], aLf[4][4];
#pragma unroll
            for (int mi = 0; mi < 4; mi++) {
                uint32_t off = aoff[mi] + (csel ^ (uint32_t)asw[mi]);
                ldm4(aHf[mi], st + off);
                ldm4(aLf[mi], st + ASZ + off);
            }
            uint32_t bHf[2][4], bLf[2][4];
#pragma unroll
            for (int nj = 0; nj < 2; nj++) {
                uint32_t off = boff[nj] + (csel ^ (uint32_t)bsw[nj]);
                ldm4(bHf[nj], st + 2 * ASZ + off);
                ldm4(bLf[nj], st + 3 * ASZ + off);
            }
#pragma unroll
            for (int mi = 0; mi < 4; mi++)
#pragma unroll
                for (int ni = 0; ni < 4; ni++) {
                    const int nj = ni >> 1, sel = ni & 1;
                    mma16816(acc[mi][ni], aHf[mi], bHf[nj][sel], bHf[nj][2 + sel]);
                    mma16816(acc[mi][ni], aHf[mi], bLf[nj][sel], bLf[nj][2 + sel]);
                    mma16816(acc[mi][ni], aLf[mi], bHf[nj][sel], bHf[nj][2 + sel]);
                }
        }
    }

    // ------------------------------- epilogue -------------------------------
#pragma unroll
    for (int mi = 0; mi < 4; mi++) {
#pragma unroll
        for (int hr = 0; hr < 2; hr++) {
            const long r = m0 + wm * 64 + mi * 16 + (lane >> 2) + hr * 8;
            float srow = 1.f;
            if (EPI == 3) srow = alpha * aux[r * 32 + z];
#pragma unroll
            for (int ni = 0; ni < 4; ni++) {
                const long c = n0 + wn * 32 + ni * 8 + (lane & 3) * 2;
                float v0 = acc[mi][ni][hr * 2 + 0];
                float v1 = acc[mi][ni][hr * 2 + 1];
                if (EPI == 1) {
                    v0 = fmaxf(v0 + aux[c], 0.f);
                    v1 = fmaxf(v1 + aux[c + 1], 0.f);
                } else if (EPI == 2) {
                    float2 rr = __ldg((const float2*)(aux + r * ldc + c));
                    v0 += rr.x;
                    v1 += rr.y;
                } else if (EPI == 3) {
                    v0 *= srow; v1 *= srow;
                }
                if (EPI == 4) {
                    bf16 h0, l0, h1, l1;
                    bf16split(v0, h0, l0); bf16split(v1, h1, l1);
                    long o = (long)z * sC + r * ldc + c;
                    OH[o] = h0; OH[o + 1] = h1;
                    OL[o] = l0; OL[o + 1] = l1;
                } else {
                    float2 vv = make_float2(v0, v1);
                    *(float2*)(C + (long)z * sC + r * ldc + c) = vv;
                }
            }
        }
    }
#undef ISSUE
}

// ------------------------------ small kernels -------------------------------

__global__ void wsplit_kernel(const float* __restrict__ in, bf16* __restrict__ H,
                              bf16* __restrict__ L, int cols)
{
    int c = blockIdx.x * 256 + threadIdx.x;
    long r = blockIdx.y;
    if (c >= cols) return;
    long o = r * cols + c;
    bf16 h, l; bf16split(in[o], h, l);
    H[o] = h; L[o] = l;
}

__global__ void rmsnorm_split_kernel(const float* __restrict__ x,
                                     const float* __restrict__ w,
                                     bf16* __restrict__ OH, bf16* __restrict__ OL)
{
    int t = blockIdx.x;
    const float4* xr = (const float4*)(x + (long)t * C_EMB);
    float s = 0.f;
    for (int i = threadIdx.x; i < C_EMB / 4; i += 256) {
        float4 v = xr[i];
        s += v.x * v.x + v.y * v.y + v.z * v.z + v.w * v.w;
    }
    __shared__ float red[256];
    red[threadIdx.x] = s;
    __syncthreads();
    for (int off = 128; off > 0; off >>= 1) {
        if (threadIdx.x < off) red[threadIdx.x] += red[threadIdx.x + off];
        __syncthreads();
    }
    float inv = rsqrtf(red[0] / (float)C_EMB + 1e-5f);
    for (int i = threadIdx.x; i < C_EMB; i += 256) {
        float v = x[(long)t * C_EMB + i] * inv * w[i];
        bf16 h, l; bf16split(v, h, l);
        OH[(long)t * C_EMB + i] = h;
        OL[(long)t * C_EMB + i] = l;
    }
}

__global__ void ropeq_kernel(const float* __restrict__ qkv,
                             const float* __restrict__ cos_, const float* __restrict__ sin_,
                             bf16* __restrict__ QH, bf16* __restrict__ QL)
{
    long idx = (long)blockIdx.x * 256 + threadIdx.x;   // 32*2048*64
    if (idx >= (long)NHEAD * T_SEQ * 64) return;
    int d = idx & 63;
    int t = (int)((idx >> 6) & (T_SEQ - 1));
    int h = (int)(idx >> 17);
    int g = h >> 2, slot = h & 3;
    const float* base = qkv + (long)t * QKV_OUT + (g * 6 + slot) * HDIM;
    float x1 = base[d], x2 = base[d + 64];
    const float* cr = cos_ + (long)t * HDIM;
    const float* sr = sin_ + (long)t * HDIM;
    long ob = ((long)h * T_SEQ + t) * HDIM;
    float o1 = x1 * cr[d]      - x2 * sr[d];
    float o2 = x2 * cr[d + 64] + x1 * sr[d + 64];
    bf16 h1, l1, h2, l2;
    bf16split(o1, h1, l1); bf16split(o2, h2, l2);
    QH[ob + d] = h1;      QL[ob + d] = l1;
    QH[ob + d + 64] = h2; QL[ob + d + 64] = l2;
}

__global__ void ropek_kernel(const float* __restrict__ qkv,
                             const float* __restrict__ cos_, const float* __restrict__ sin_,
                             bf16* __restrict__ KH, bf16* __restrict__ KL)
{
    long idx = (long)blockIdx.x * 256 + threadIdx.x;   // 8*2048*64
    if (idx >= (long)NKV * T_SEQ * 64) return;
    int d = idx & 63;
    int t = (int)((idx >> 6) & (T_SEQ - 1));
    int g = (int)(idx >> 17);
    const float* base = qkv + (long)t * QKV_OUT + (g * 6 + 4) * HDIM;
    float x1 = base[d], x2 = base[d + 64];
    const float* cr = cos_ + (long)t * HDIM;
    const float* sr = sin_ + (long)t * HDIM;
    long ob = ((long)g * T_SEQ + t) * HDIM;
    float o1 = x1 * cr[d]      - x2 * sr[d];
    float o2 = x2 * cr[d + 64] + x1 * sr[d + 64];
    bf16 h1, l1, h2, l2;
    bf16split(o1, h1, l1); bf16split(o2, h2, l2);
    KH[ob + d] = h1;      KL[ob + d] = l1;
    KH[ob + d + 64] = h2; KL[ob + d + 64] = l2;
}

// Vt[g][d][t] <- qkv[t][g*768 + 640 + d]
__global__ void vsplit_kernel(const float* __restrict__ qkv,
                              bf16* __restrict__ VH, bf16* __restrict__ VL)
{
    long idx = (long)blockIdx.x * 256 + threadIdx.x;   // 8*128*2048
    if (idx >= (long)NKV * HDIM * T_SEQ) return;
    int t = idx & 2047;
    int d = (int)((idx >> 11) & 127);
    int g = (int)(idx >> 18);
    float v = qkv[(long)t * QKV_OUT + g * 768 + 640 + d];
    bf16 h, l; bf16split(v, h, l);
    VH[idx] = h; VL[idx] = l;
}

__global__ void scalet_kernel(const float* __restrict__ scaling,
                              float* __restrict__ scale_t)
{
    int t = blockIdx.x;
    int w = threadIdx.x >> 5, lane = threadIdx.x & 31;
    const float* p = scaling + (long)t * C_EMB + w * HDIM;
    float s = p[lane] + p[lane + 32] + p[lane + 64] + p[lane + 96];
    for (int off = 16; off; off >>= 1) s += __shfl_down_sync(0xffffffffu, s, off);
    if (lane == 0) scale_t[t * NHEAD + w] = s * (1.f / 128.f);
}

// softmax over 2048, then writes bf16 hi/lo planes in place over the fp32 row
__global__ void softmax_kernel(float* __restrict__ scores)
{
    long row = blockIdx.x;
    float* p = scores + row * (long)T_SEQ;
    int tid = threadIdx.x;
    float v[8];
    float m = -1e30f;
#pragma unroll
    for (int i = 0; i < 8; i++) { v[i] = p[tid + i * 256]; m = fmaxf(m, v[i]); }
    __shared__ float red[256];
    red[tid] = m; __syncthreads();
    for (int off = 128; off; off >>= 1) {
        if (tid < off) red[tid] = fmaxf(red[tid], red[tid + off]);
        __syncthreads();
    }
    m = red[0]; __syncthreads();
    float s = 0.f;
#pragma unroll
    for (int i = 0; i < 8; i++) { v[i] = __expf(v[i] - m); s += v[i]; }
    red[tid] = s; __syncthreads();
    for (int off = 128; off; off >>= 1) {
        if (tid < off) red[tid] += red[tid + off];
        __syncthreads();
    }
    float inv = 1.f / red[0];
    bf16* ph = (bf16*)p;
    bf16* pl = ph + 2048;
#pragma unroll
    for (int i = 0; i < 8; i++) {
        int j = tid + i * 256;
        float pv = v[i] * inv;
        bf16 h, l; bf16split(pv, h, l);
        ph[j] = h; pl[j] = l;
    }
}

__global__ void silumul_split_kernel(const float* __restrict__ g, const float* __restrict__ u,
                                     bf16* __restrict__ GH, bf16* __restrict__ GL, long n)
{
    long i = (long)blockIdx.x * 256 + threadIdx.x;
    if (i < n) {
        float gv = g[i], uv = u[i];
        float v = gv * uv / (1.f + __expf(-gv));
        bf16 h, l; bf16split(v, h, l);
        GH[i] = h; GL[i] = l;
    }
}

// ------------------------------- launch -------------------------------------

extern "C" void kernel_launch(void* const* d_in, const int* in_sizes, int n_in,
                              void* d_out, int out_size)
{
    const float* x       = (const float*)d_in[0];
    const float* cosp    = (const float*)d_in[1];
    const float* sinp    = (const float*)d_in[2];
    const float* norm1_w = (const float*)d_in[3];
    const float* norm2_w = (const float*)d_in[4];
    const float* attn_w  = (const float*)d_in[5];
    const float* proj_w  = (const float*)d_in[6];
    const float* scale_w = (const float*)d_in[7];
    const float* scale_b = (const float*)d_in[8];
    const float* gate_w  = (const float*)d_in[9];
    const float* up_w    = (const float*)d_in[10];
    const float* down_w  = (const float*)d_in[11];
    float* out = (float*)d_out;

    float *qkv, *scaling, *scale_t, *scores, *x2, *gateb, *upb;
    bf16 *n1h, *n1l, *n2h, *n2l, *yh, *yl, *qh, *ql, *kh, *kl, *vth, *vtl, *gh, *gl;
    bf16 *aWh, *aWl, *sWh, *sWl, *pWh, *pWl, *gWh, *gWl, *uWh, *uWl, *dWh, *dWl;
    cudaGetSymbolAddress((void**)&qkv, g_qkv);
    cudaGetSymbolAddress((void**)&scaling, g_scaling);
    cudaGetSymbolAddress((void**)&scale_t, g_scale_t);
    cudaGetSymbolAddress((void**)&scores, g_scores);
    cudaGetSymbolAddress((void**)&x2, g_x2);
    cudaGetSymbolAddress((void**)&gateb, g_gate);
    cudaGetSymbolAddress((void**)&upb, g_up);
    cudaGetSymbolAddress((void**)&n1h, g_n1h); cudaGetSymbolAddress((void**)&n1l, g_n1l);
    cudaGetSymbolAddress((void**)&n2h, g_n2h); cudaGetSymbolAddress((void**)&n2l, g_n2l);
    cudaGetSymbolAddress((void**)&yh, g_yh);   cudaGetSymbolAddress((void**)&yl, g_yl);
    cudaGetSymbolAddress((void**)&qh, g_qh);   cudaGetSymbolAddress((void**)&ql, g_ql);
    cudaGetSymbolAddress((void**)&kh, g_kh);   cudaGetSymbolAddress((void**)&kl, g_kl);
    cudaGetSymbolAddress((void**)&vth, g_vth); cudaGetSymbolAddress((void**)&vtl, g_vtl);
    cudaGetSymbolAddress((void**)&gh, g_gh);   cudaGetSymbolAddress((void**)&gl, g_gl);
    cudaGetSymbolAddress((void**)&aWh, g_aWh); cudaGetSymbolAddress((void**)&aWl, g_aWl);
    cudaGetSymbolAddress((void**)&sWh, g_sWh); cudaGetSymbolAddress((void**)&sWl, g_sWl);
    cudaGetSymbolAddress((void**)&pWh, g_pWh); cudaGetSymbolAddress((void**)&pWl, g_pWl);
    cudaGetSymbolAddress((void**)&gWh, g_gWh); cudaGetSymbolAddress((void**)&gWl, g_gWl);
    cudaGetSymbolAddress((void**)&uWh, g_uWh); cudaGetSymbolAddress((void**)&uWl, g_uWl);
    cudaGetSymbolAddress((void**)&dWh, g_dWh); cudaGetSymbolAddress((void**)&dWl, g_dWl);

    const int SMEM = 3 * STG;   // 196608
    cudaFuncSetAttribute(tcmm<0>, cudaFuncAttributeMaxDynamicSharedMemorySize, SMEM);
    cudaFuncSetAttribute(tcmm<1>, cudaFuncAttributeMaxDynamicSharedMemorySize, SMEM);
    cudaFuncSetAttribute(tcmm<2>, cudaFuncAttributeMaxDynamicSharedMemorySize, SMEM);
    cudaFuncSetAttribute(tcmm<3>, cudaFuncAttributeMaxDynamicSharedMemorySize, SMEM);
    cudaFuncSetAttribute(tcmm<4>, cudaFuncAttributeMaxDynamicSharedMemorySize, SMEM);

    const float sf = 0.08838834764831843f;   // 1/sqrt(128)

    // weight hi/lo splits (recomputed every call: deterministic)
    wsplit_kernel<<<dim3(C_EMB / 256, QKV_OUT), 256>>>(attn_w, aWh, aWl, C_EMB);
    wsplit_kernel<<<dim3(C_EMB / 256, C_EMB), 256>>>(scale_w, sWh, sWl, C_EMB);
    wsplit_kernel<<<dim3(C_EMB / 256, C_EMB), 256>>>(proj_w, pWh, pWl, C_EMB);
    wsplit_kernel<<<dim3(C_EMB / 256, FFN_DIM), 256>>>(gate_w, gWh, gWl, C_EMB);
    wsplit_kernel<<<dim3(C_EMB / 256, FFN_DIM), 256>>>(up_w, uWh, uWl, C_EMB);
    wsplit_kernel<<<dim3(FFN_DIM / 256, C_EMB), 256>>>(down_w, dWh, dWl, FFN_DIM);

    // 1. n1 = rmsnorm(x) -> bf16 hi/lo
    rmsnorm_split_kernel<<<T_SEQ, 256>>>(x, norm1_w, n1h, n1l);

    // 2. qkv = n1 @ attn_w^T  (fp32 out)
    tcmm<0><<<dim3(16, QKV_OUT / 128, 1), 256, SMEM>>>(
        n1h, n1l, aWh, aWl, qkv, nullptr, nullptr,
        C_EMB, C_EMB, C_EMB, QKV_OUT, 0, 0, 0, 1, nullptr, 0.f);

    // 3. scaling = relu(n1 @ scale_w^T + scale_b)
    tcmm<1><<<dim3(16, C_EMB / 128, 1), 256, SMEM>>>(
        n1h, n1l, sWh, sWl, scaling, nullptr, nullptr,
        C_EMB, C_EMB, C_EMB, C_EMB, 0, 0, 0, 1, scale_b, 0.f);

    // 4. per-(t,h) mean
    scalet_kernel<<<T_SEQ, 1024>>>(scaling, scale_t);

    // 5. rope + splits
    ropeq_kernel<<<(NHEAD * T_SEQ * 64) / 256, 256>>>(qkv, cosp, sinp, qh, ql);
    ropek_kernel<<<(NKV * T_SEQ * 64) / 256, 256>>>(qkv, cosp, sinp, kh, kl);
    vsplit_kernel<<<(NKV * HDIM * T_SEQ) / 256, 256>>>(qkv, vth, vtl);

    // 6. scores[h] = (Q[h] @ K[g]^T) * sf * scale_t[:,h]
    tcmm<3><<<dim3(16, 16, NHEAD), 256, SMEM>>>(
        qh, ql, kh, kl, scores, nullptr, nullptr,
        HDIM, HDIM, HDIM, T_SEQ,
        (long)T_SEQ * HDIM, (long)T_SEQ * HDIM, (long)T_SEQ * T_SEQ, 4,
        scale_t, sf);

    // 7. softmax (writes P hi/lo bf16 in place)
    softmax_kernel<<<NHEAD * T_SEQ, 256>>>(scores);

    // 8. y[:, h*128:+128] = P[h] @ V[g]  -> bf16 hi/lo planes
    tcmm<4><<<dim3(16, 1, NHEAD), 256, SMEM>>>(
        (const bf16*)scores, (const bf16*)scores + 2048, vth, vtl,
        nullptr, yh, yl,
        T_SEQ, 2 * T_SEQ, T_SEQ, C_EMB,
        (long)T_SEQ * 2 * T_SEQ, (long)HDIM * T_SEQ, (long)HDIM, 4,
        nullptr, 0.f);

    // 9. x2 = x + y @ proj_w^T
    tcmm<2><<<dim3(16, C_EMB / 128, 1), 256, SMEM>>>(
        yh, yl, pWh, pWl, x2, nullptr, nullptr,
        C_EMB, C_EMB, C_EMB, C_EMB, 0, 0, 0, 1, x, 0.f);

    // 10. n2 = rmsnorm(x2)
    rmsnorm_split_kernel<<<T_SEQ, 256>>>(x2, norm2_w, n2h, n2l);

    // 11/12. gate & up
    tcmm<0><<<dim3(16, FFN_DIM / 128, 1), 256, SMEM>>>(
        n2h, n2l, gWh, gWl, gateb, nullptr, nullptr,
        C_EMB, C_EMB, C_EMB, FFN_DIM, 0, 0, 0, 1, nullptr, 0.f);
    tcmm<0><<<dim3(16, FFN_DIM / 128, 1), 256, SMEM>>>(
        n2h, n2l, uWh, uWl, upb, nullptr, nullptr,
        C_EMB, C_EMB, C_EMB, FFN_DIM, 0, 0, 0, 1, nullptr, 0.f);

    // 13. gh/gl = split(silu(gate) * up)
    {
        long n = (long)T_SEQ * FFN_DIM;
        silumul_split_kernel<<<(unsigned)((n + 255) / 256), 256>>>(gateb, upb, gh, gl, n);
    }

    // 14. out = x2 + (silu*up) @ down_w^T
    tcmm<2><<<dim3(16, C_EMB / 128, 1), 256, SMEM>>>(
        gh, gl, dWh, dWl, out, nullptr, nullptr,
        FFN_DIM, FFN_DIM, FFN_DIM, C_EMB, 0, 0, 0, 1, x2, 0.f);
}

// round 11
// speedup vs baseline: 2.6619x; 1.0263x over previous
#include <cuda_runtime.h>
#include <cuda_bf16.h>
#include <cstdint>

// ---------------------------------------------------------------------------
// Transformer block via mma.sync bf16 (sm_80 PTX path, compiles at compute_103).
// All GEMMs: C = A @ B^T, A/B pre-split into bf16 hi/lo planes; fp32 accum of
// AhBh + AhBl + AlBh gives fp32-class accuracy.
// 128x128x32 CTA tile, 3-stage cp.async pipeline (96KB smem), 2 CTAs/SM.
// ---------------------------------------------------------------------------

#define T_SEQ   2048
#define C_EMB   4096
#define QKV_OUT 6144
#define FFN_DIM 11008
#define NHEAD   32
#define NKV     8
#define HDIM    128

typedef __nv_bfloat16 bf16;

// ------------------------- scratch (static device memory) ------------------
__device__ float g_qkv[T_SEQ * QKV_OUT];
__device__ float g_scaling[T_SEQ * C_EMB];
__device__ float g_scale_t[T_SEQ * NHEAD];
__device__ float g_scores[(long)NHEAD * T_SEQ * T_SEQ];   // reused as P hi/lo bf16
__device__ float g_x2[T_SEQ * C_EMB];
__device__ float g_gate[(long)T_SEQ * FFN_DIM];
__device__ float g_up[(long)T_SEQ * FFN_DIM];

__device__ bf16 g_n1h[T_SEQ * C_EMB], g_n1l[T_SEQ * C_EMB];
__device__ bf16 g_n2h[T_SEQ * C_EMB], g_n2l[T_SEQ * C_EMB];
__device__ bf16 g_yh[T_SEQ * C_EMB],  g_yl[T_SEQ * C_EMB];
__device__ bf16 g_qh[(long)NHEAD * T_SEQ * HDIM], g_ql[(long)NHEAD * T_SEQ * HDIM];
__device__ bf16 g_kh[(long)NKV * T_SEQ * HDIM],   g_kl[(long)NKV * T_SEQ * HDIM];
__device__ bf16 g_vth[(long)NKV * HDIM * T_SEQ],  g_vtl[(long)NKV * HDIM * T_SEQ];
__device__ bf16 g_gh[(long)T_SEQ * FFN_DIM], g_gl[(long)T_SEQ * FFN_DIM];

__device__ bf16 g_aWh[(long)QKV_OUT * C_EMB], g_aWl[(long)QKV_OUT * C_EMB];
__device__ bf16 g_sWh[(long)C_EMB * C_EMB],   g_sWl[(long)C_EMB * C_EMB];
__device__ bf16 g_pWh[(long)C_EMB * C_EMB],   g_pWl[(long)C_EMB * C_EMB];
__device__ bf16 g_gWh[(long)FFN_DIM * C_EMB], g_gWl[(long)FFN_DIM * C_EMB];
__device__ bf16 g_uWh[(long)FFN_DIM * C_EMB], g_uWl[(long)FFN_DIM * C_EMB];
__device__ bf16 g_dWh[(long)C_EMB * FFN_DIM], g_dWl[(long)C_EMB * FFN_DIM];

// ------------------------------ PTX helpers ---------------------------------
__device__ __forceinline__ uint32_t smem_u32(const void* p) {
    uint32_t a;
    asm("{ .reg .u64 t; cvta.to.shared.u64 t, %1; cvt.u32.u64 %0, t; }" : "=r"(a) : "l"(p));
    return a;
}

__device__ __forceinline__ void cp16(uint32_t dst, const void* src) {
    asm volatile("cp.async.cg.shared.global [%0], [%1], 16;" :: "r"(dst), "l"(src));
}
#define CP_COMMIT() asm volatile("cp.async.commit_group;" ::: "memory")
#define CP_WAIT1()  asm volatile("cp.async.wait_group 1;" ::: "memory")
#define CP_WAIT0()  asm volatile("cp.async.wait_group 0;" ::: "memory")

__device__ __forceinline__ void ldm4(uint32_t (&r)[4], uint32_t addr) {
    asm volatile("ldmatrix.sync.aligned.m8n8.x4.shared.b16 {%0,%1,%2,%3}, [%4];"
        : "=r"(r[0]), "=r"(r[1]), "=r"(r[2]), "=r"(r[3]) : "r"(addr));
}

__device__ __forceinline__ void mma16816(float (&c)[4], const uint32_t (&a)[4],
                                         uint32_t b0, uint32_t b1) {
    asm volatile("mma.sync.aligned.m16n8k16.row.col.f32.bf16.bf16.f32 "
        "{%0,%1,%2,%3}, {%4,%5,%6,%7}, {%8,%9}, {%0,%1,%2,%3};"
        : "+f"(c[0]), "+f"(c[1]), "+f"(c[2]), "+f"(c[3])
        : "r"(a[0]), "r"(a[1]), "r"(a[2]), "r"(a[3]), "r"(b0), "r"(b1));
}

__device__ __forceinline__ void bf16split(float v, bf16& h, bf16& l) {
    h = __float2bfloat16(v);
    l = __float2bfloat16(v - __bfloat162float(h));
}

// ------------------------------ GEMM kernel ---------------------------------
// C[m][n] = sum_k A[m,k]*B[n,k]; tiles 128x128, K step 32.
// Smem stage (32 KB): Ah[128x32] Al Bh Bl, 64B swizzled rows. 3 stages.
// EPI: 0 none, 1 relu(acc+aux[col]), 2 acc+aux[row*ldc+col],
//      3 acc*alpha*aux[row*32+z], 4 bf16-split store to OH/OL.
#define ASZ2 8192
#define STG2 32768

template<int EPI>
__global__ __launch_bounds__(256, 2)
void tcmm(const bf16* __restrict__ Ah, const bf16* __restrict__ Al,
          const bf16* __restrict__ Bh, const bf16* __restrict__ Bl,
          float* __restrict__ C, bf16* __restrict__ OH, bf16* __restrict__ OL,
          int K, int lda, int ldb, int ldc,
          long sA, long sB, long sC, int bdiv,
          const float* __restrict__ aux, float alpha)
{
    extern __shared__ char sm[];
    const uint32_t sbase = smem_u32(sm);

    const int tid = threadIdx.x, wid = tid >> 5, lane = tid & 31;
    const int wm = wid & 1, wn = wid >> 1;        // 2 x 4 warp grid; warp tile 64x32
    const int half = lane >> 4;
    const int z = blockIdx.z;
    Ah += (long)z * sA;  Al += (long)z * sA;
    { long bo = (long)(z / bdiv) * sB; Bh += bo; Bl += bo; }
    const long m0 = (long)blockIdx.x * 128;
    const long n0 = (long)blockIdx.y * 128;

    // ldmatrix per-thread row offsets (64B rows, 2-bit swizzle)
    int aoff[4], asw[4], boff[2], bsw[2];
#pragma unroll
    for (int mi = 0; mi < 4; mi++) {
        int r = wm * 64 + mi * 16 + (lane & 15);
        aoff[mi] = r * 64; asw[mi] = (r & 3) << 4;
    }
#pragma unroll
    for (int nj = 0; nj < 2; nj++) {
        int r = wn * 32 + nj * 16 + (lane & 15);
        boff[nj] = r * 64; bsw[nj] = (r & 3) << 4;
    }

    float acc[4][4][4];
#pragma unroll
    for (int mi = 0; mi < 4; mi++)
#pragma unroll
        for (int ni = 0; ni < 4; ni++)
#pragma unroll
            for (int j = 0; j < 4; j++) acc[mi][ni][j] = 0.f;

    const int niter = K >> 5;

    // loader: row = (tid>>2)+i*64, chunk c = tid&3
    const int lr = tid >> 2, lc = tid & 3;

#define ISSUE(it_) do {                                                         \
    int _s = (it_) % 3;                                                         \
    long _k0 = (long)(it_) << 5;                                                \
    uint32_t _st = sbase + _s * STG2;                                           \
    _Pragma("unroll")                                                           \
    for (int i = 0; i < 2; i++) {                                               \
        int row = lr + i * 64;                                                  \
        uint32_t off = row * 64 + (((lc ^ (row & 3))) << 4);                    \
        long ga = (m0 + row) * (long)lda + _k0 + lc * 8;                        \
        long gb = (n0 + row) * (long)ldb + _k0 + lc * 8;                        \
        cp16(_st + off,              Ah + ga);                                  \
        cp16(_st + ASZ2 + off,       Al + ga);                                  \
        cp16(_st + 2 * ASZ2 + off,   Bh + gb);                                  \
        cp16(_st + 3 * ASZ2 + off,   Bl + gb);                                  \
    }                                                                           \
    CP_COMMIT();                                                                \
} while (0)

    ISSUE(0);
    ISSUE(1);

    for (int it = 0; it < niter; ++it) {
        if (it + 1 < niter) CP_WAIT1(); else CP_WAIT0();
        __syncthreads();
        if (it + 2 < niter) ISSUE(it + 2);

        const uint32_t st = sbase + (it % 3) * STG2;
#pragma unroll
        for (int ks = 0; ks < 2; ks++) {
            const uint32_t csel = (uint32_t)(((ks << 1) | half) << 4);
            uint32_t bHf[2][4], bLf[2][4];
#pragma unroll
            for (int nj = 0; nj < 2; nj++) {
                uint32_t off = boff[nj] + (csel ^ (uint32_t)bsw[nj]);
                ldm4(bHf[nj], st + 2 * ASZ2 + off);
                ldm4(bLf[nj], st + 3 * ASZ2 + off);
            }
#pragma unroll
            for (int mi = 0; mi < 4; mi++) {
                uint32_t aH[4], aL[4];
                uint32_t off = aoff[mi] + (csel ^ (uint32_t)asw[mi]);
                ldm4(aH, st + off);
                ldm4(aL, st + ASZ2 + off);
#pragma unroll
                for (int ni = 0; ni < 4; ni++) {
                    const int nj = ni >> 1, sel = ni & 1;
                    mma16816(acc[mi][ni], aH, bHf[nj][sel], bHf[nj][2 + sel]);
                    mma16816(acc[mi][ni], aH, bLf[nj][sel], bLf[nj][2 + sel]);
                    mma16816(acc[mi][ni], aL, bHf[nj][sel], bHf[nj][2 + sel]);
                }
            }
        }
    }

    // ------------------------------- epilogue -------------------------------
#pragma unroll
    for (int mi = 0; mi < 4; mi++) {
#pragma unroll
        for (int hr = 0; hr < 2; hr++) {
            const long r = m0 + wm * 64 + mi * 16 + (lane >> 2) + hr * 8;
            float srow = 1.f;
            if (EPI == 3) srow = alpha * aux[r * 32 + z];
#pragma unroll
            for (int ni = 0; ni < 4; ni++) {
                const long c = n0 + wn * 32 + ni * 8 + (lane & 3) * 2;
                float v0 = acc[mi][ni][hr * 2 + 0];
                float v1 = acc[mi][ni][hr * 2 + 1];
                if (EPI == 1) {
                    v0 = fmaxf(v0 + aux[c], 0.f);
                    v1 = fmaxf(v1 + aux[c + 1], 0.f);
                } else if (EPI == 2) {
                    float2 rr = __ldg((const float2*)(aux + r * ldc + c));
                    v0 += rr.x;
                    v1 += rr.y;
                } else if (EPI == 3) {
                    v0 *= srow; v1 *= srow;
                }
                if (EPI == 4) {
                    bf16 h0, l0, h1, l1;
                    bf16split(v0, h0, l0); bf16split(v1, h1, l1);
                    long o = (long)z * sC + r * ldc + c;
                    OH[o] = h0; OH[o + 1] = h1;
                    OL[o] = l0; OL[o + 1] = l1;
                } else {
                    float2 vv = make_float2(v0, v1);
                    *(float2*)(C + (long)z * sC + r * ldc + c) = vv;
                }
            }
        }
    }
#undef ISSUE
}

// ------------------------------ small kernels -------------------------------

// vectorized fp32 -> bf16 hi/lo split: 8 elements per thread
__global__ void wsplit_kernel(const float* __restrict__ in, bf16* __restrict__ H,
                              bf16* __restrict__ L, int cols)
{
    long c8 = ((long)blockIdx.x * 256 + threadIdx.x) * 8;
    if (c8 >= cols) return;
    long o = (long)blockIdx.y * cols + c8;
    float4 a = *(const float4*)(in + o);
    float4 b = *(const float4*)(in + o + 4);
    bf16 hv[8], lv[8];
    const float* f = (const float*)&a;
#pragma unroll
    for (int j = 0; j < 4; j++) bf16split(f[j], hv[j], lv[j]);
    f = (const float*)&b;
#pragma unroll
    for (int j = 0; j < 4; j++) bf16split(f[j], hv[4 + j], lv[4 + j]);
    *(uint4*)(H + o) = *(const uint4*)hv;
    *(uint4*)(L + o) = *(const uint4*)lv;
}

__global__ void rmsnorm_split_kernel(const float* __restrict__ x,
                                     const float* __restrict__ w,
                                     bf16* __restrict__ OH, bf16* __restrict__ OL)
{
    int t = blockIdx.x;
    const float4* xr = (const float4*)(x + (long)t * C_EMB);
    float s = 0.f;
    for (int i = threadIdx.x; i < C_EMB / 4; i += 256) {
        float4 v = xr[i];
        s += v.x * v.x + v.y * v.y + v.z * v.z + v.w * v.w;
    }
    __shared__ float red[256];
    red[threadIdx.x] = s;
    __syncthreads();
    for (int off = 128; off > 0; off >>= 1) {
        if (threadIdx.x < off) red[threadIdx.x] += red[threadIdx.x + off];
        __syncthreads();
    }
    float inv = rsqrtf(red[0] / (float)C_EMB + 1e-5f);
    const float4* wv = (const float4*)w;
    for (int i = threadIdx.x; i < C_EMB / 4; i += 256) {
        float4 v = xr[i];
        float4 ww = wv[i];
        bf16 hv[4], lv[4];
        bf16split(v.x * inv * ww.x, hv[0], lv[0]);
        bf16split(v.y * inv * ww.y, hv[1], lv[1]);
        bf16split(v.z * inv * ww.z, hv[2], lv[2]);
        bf16split(v.w * inv * ww.w, hv[3], lv[3]);
        *(uint2*)(OH + (long)t * C_EMB + i * 4) = *(const uint2*)hv;
        *(uint2*)(OL + (long)t * C_EMB + i * 4) = *(const uint2*)lv;
    }
}

__global__ void ropeq_kernel(const float* __restrict__ qkv,
                             const float* __restrict__ cos_, const float* __restrict__ sin_,
                             bf16* __restrict__ QH, bf16* __restrict__ QL)
{
    long idx = (long)blockIdx.x * 256 + threadIdx.x;   // 32*2048*64
    if (idx >= (long)NHEAD * T_SEQ * 64) return;
    int d = idx & 63;
    int t = (int)((idx >> 6) & (T_SEQ - 1));
    int h = (int)(idx >> 17);
    int g = h >> 2, slot = h & 3;
    const float* base = qkv + (long)t * QKV_OUT + (g * 6 + slot) * HDIM;
    float x1 = base[d], x2 = base[d + 64];
    const float* cr = cos_ + (long)t * HDIM;
    const float* sr = sin_ + (long)t * HDIM;
    long ob = ((long)h * T_SEQ + t) * HDIM;
    float o1 = x1 * cr[d]      - x2 * sr[d];
    float o2 = x2 * cr[d + 64] + x1 * sr[d + 64];
    bf16 h1, l1, h2, l2;
    bf16split(o1, h1, l1); bf16split(o2, h2, l2);
    QH[ob + d] = h1;      QL[ob + d] = l1;
    QH[ob + d + 64] = h2; QL[ob + d + 64] = l2;
}

__global__ void ropek_kernel(const float* __restrict__ qkv,
                             const float* __restrict__ cos_, const float* __restrict__ sin_,
                             bf16* __restrict__ KH, bf16* __restrict__ KL)
{
    long idx = (long)blockIdx.x * 256 + threadIdx.x;   // 8*2048*64
    if (idx >= (long)NKV * T_SEQ * 64) return;
    int d = idx & 63;
    int t = (int)((idx >> 6) & (T_SEQ - 1));
    int g = (int)(idx >> 17);
    const float* base = qkv + (long)t * QKV_OUT + (g * 6 + 4) * HDIM;
    float x1 = base[d], x2 = base[d + 64];
    const float* cr = cos_ + (long)t * HDIM;
    const float* sr = sin_ + (long)t * HDIM;
    long ob = ((long)g * T_SEQ + t) * HDIM;
    float o1 = x1 * cr[d]      - x2 * sr[d];
    float o2 = x2 * cr[d + 64] + x1 * sr[d + 64];
    bf16 h1, l1, h2, l2;
    bf16split(o1, h1, l1); bf16split(o2, h2, l2);
    KH[ob + d] = h1;      KL[ob + d] = l1;
    KH[ob + d + 64] = h2; KL[ob + d + 64] = l2;
}

// Vt[g][d][t] <- qkv[t][g*768 + 640 + d]
__global__ void vsplit_kernel(const float* __restrict__ qkv,
                              bf16* __restrict__ VH, bf16* __restrict__ VL)
{
    long idx = (long)blockIdx.x * 256 + threadIdx.x;   // 8*128*2048
    if (idx >= (long)NKV * HDIM * T_SEQ) return;
    int t = idx & 2047;
    int d = (int)((idx >> 11) & 127);
    int g = (int)(idx >> 18);
    float v = qkv[(long)t * QKV_OUT + g * 768 + 640 + d];
    bf16 h, l; bf16split(v, h, l);
    VH[idx] = h; VL[idx] = l;
}

__global__ void scalet_kernel(const float* __restrict__ scaling,
                              float* __restrict__ scale_t)
{
    int t = blockIdx.x;
    int w = threadIdx.x >> 5, lane = threadIdx.x & 31;
    const float* p = scaling + (long)t * C_EMB + w * HDIM;
    float s = p[lane] + p[lane + 32] + p[lane + 64] + p[lane + 96];
    for (int off = 16; off; off >>= 1) s += __shfl_down_sync(0xffffffffu, s, off);
    if (lane == 0) scale_t[t * NHEAD + w] = s * (1.f / 128.f);
}

// softmax over 2048, then writes bf16 hi/lo planes in place over the fp32 row
__global__ void softmax_kernel(float* __restrict__ scores)
{
    long row = blockIdx.x;
    float* p = scores + row * (long)T_SEQ;
    int tid = threadIdx.x;
    float v[8];
    float m = -1e30f;
#pragma unroll
    for (int i = 0; i < 8; i++) { v[i] = p[tid + i * 256]; m = fmaxf(m, v[i]); }
    __shared__ float red[256];
    red[tid] = m; __syncthreads();
    for (int off = 128; off; off >>= 1) {
        if (tid < off) red[tid] = fmaxf(red[tid], red[tid + off]);
        __syncthreads();
    }
    m = red[0]; __syncthreads();
    float s = 0.f;
#pragma unroll
    for (int i = 0; i < 8; i++) { v[i] = __expf(v[i] - m); s += v[i]; }
    red[tid] = s; __syncthreads();
    for (int off = 128; off; off >>= 1) {
        if (tid < off) red[tid] += red[tid + off];
        __syncthreads();
    }
    float inv = 1.f / red[0];
    bf16* ph = (bf16*)p;
    bf16* pl = ph + 2048;
#pragma unroll
    for (int i = 0; i < 8; i++) {
        int j = tid + i * 256;
        float pv = v[i] * inv;
        bf16 h, l; bf16split(pv, h, l);
        ph[j] = h; pl[j] = l;
    }
}

// vectorized: 4 elements per thread
__global__ void silumul_split_kernel(const float* __restrict__ g, const float* __restrict__ u,
                                     bf16* __restrict__ GH, bf16* __restrict__ GL, long n)
{
    long i4 = ((long)blockIdx.x * 256 + threadIdx.x) * 4;
    if (i4 >= n) return;
    float4 gv = *(const float4*)(g + i4);
    float4 uv = *(const float4*)(u + i4);
    bf16 hv[4], lv[4];
    bf16split(gv.x * uv.x / (1.f + __expf(-gv.x)), hv[0], lv[0]);
    bf16split(gv.y * uv.y / (1.f + __expf(-gv.y)), hv[1], lv[1]);
    bf16split(gv.z * uv.z / (1.f + __expf(-gv.z)), hv[2], lv[2]);
    bf16split(gv.w * uv.w / (1.f + __expf(-gv.w)), hv[3], lv[3]);
    *(uint2*)(GH + i4) = *(const uint2*)hv;
    *(uint2*)(GL + i4) = *(const uint2*)lv;
}

// ------------------------------- launch -------------------------------------

extern "C" void kernel_launch(void* const* d_in, const int* in_sizes, int n_in,
                              void* d_out, int out_size)
{
    const float* x       = (const float*)d_in[0];
    const float* cosp    = (const float*)d_in[1];
    const float* sinp    = (const float*)d_in[2];
    const float* norm1_w = (const float*)d_in[3];
    const float* norm2_w = (const float*)d_in[4];
    const float* attn_w  = (const float*)d_in[5];
    const float* proj_w  = (const float*)d_in[6];
    const float* scale_w = (const float*)d_in[7];
    const float* scale_b = (const float*)d_in[8];
    const float* gate_w  = (const float*)d_in[9];
    const float* up_w    = (const float*)d_in[10];
    const float* down_w  = (const float*)d_in[11];
    float* out = (float*)d_out;

    float *qkv, *scaling, *scale_t, *scores, *x2, *gateb, *upb;
    bf16 *n1h, *n1l, *n2h, *n2l, *yh, *yl, *qh, *ql, *kh, *kl, *vth, *vtl, *gh, *gl;
    bf16 *aWh, *aWl, *sWh, *sWl, *pWh, *pWl, *gWh, *gWl, *uWh, *uWl, *dWh, *dWl;
    cudaGetSymbolAddress((void**)&qkv, g_qkv);
    cudaGetSymbolAddress((void**)&scaling, g_scaling);
    cudaGetSymbolAddress((void**)&scale_t, g_scale_t);
    cudaGetSymbolAddress((void**)&scores, g_scores);
    cudaGetSymbolAddress((void**)&x2, g_x2);
    cudaGetSymbolAddress((void**)&gateb, g_gate);
    cudaGetSymbolAddress((void**)&upb, g_up);
    cudaGetSymbolAddress((void**)&n1h, g_n1h); cudaGetSymbolAddress((void**)&n1l, g_n1l);
    cudaGetSymbolAddress((void**)&n2h, g_n2h); cudaGetSymbolAddress((void**)&n2l, g_n2l);
    cudaGetSymbolAddress((void**)&yh, g_yh);   cudaGetSymbolAddress((void**)&yl, g_yl);
    cudaGetSymbolAddress((void**)&qh, g_qh);   cudaGetSymbolAddress((void**)&ql, g_ql);
    cudaGetSymbolAddress((void**)&kh, g_kh);   cudaGetSymbolAddress((void**)&kl, g_kl);
    cudaGetSymbolAddress((void**)&vth, g_vth); cudaGetSymbolAddress((void**)&vtl, g_vtl);
    cudaGetSymbolAddress((void**)&gh, g_gh);   cudaGetSymbolAddress((void**)&gl, g_gl);
    cudaGetSymbolAddress((void**)&aWh, g_aWh); cudaGetSymbolAddress((void**)&aWl, g_aWl);
    cudaGetSymbolAddress((void**)&sWh, g_sWh); cudaGetSymbolAddress((void**)&sWl, g_sWl);
    cudaGetSymbolAddress((void**)&pWh, g_pWh); cudaGetSymbolAddress((void**)&pWl, g_pWl);
    cudaGetSymbolAddress((void**)&gWh, g_gWh); cudaGetSymbolAddress((void**)&gWl, g_gWl);
    cudaGetSymbolAddress((void**)&uWh, g_uWh); cudaGetSymbolAddress((void**)&uWl, g_uWl);
    cudaGetSymbolAddress((void**)&dWh, g_dWh); cudaGetSymbolAddress((void**)&dWl, g_dWl);

    const int SMEM = 3 * STG2;   // 98304
    cudaFuncSetAttribute(tcmm<0>, cudaFuncAttributeMaxDynamicSharedMemorySize, SMEM);
    cudaFuncSetAttribute(tcmm<1>, cudaFuncAttributeMaxDynamicSharedMemorySize, SMEM);
    cudaFuncSetAttribute(tcmm<2>, cudaFuncAttributeMaxDynamicSharedMemorySize, SMEM);
    cudaFuncSetAttribute(tcmm<3>, cudaFuncAttributeMaxDynamicSharedMemorySize, SMEM);
    cudaFuncSetAttribute(tcmm<4>, cudaFuncAttributeMaxDynamicSharedMemorySize, SMEM);

    const float sf = 0.08838834764831843f;   // 1/sqrt(128)

    // weight hi/lo splits (recomputed every call: deterministic)
    wsplit_kernel<<<dim3((C_EMB / 8 + 255) / 256, QKV_OUT), 256>>>(attn_w, aWh, aWl, C_EMB);
    wsplit_kernel<<<dim3((C_EMB / 8 + 255) / 256, C_EMB), 256>>>(scale_w, sWh, sWl, C_EMB);
    wsplit_kernel<<<dim3((C_EMB / 8 + 255) / 256, C_EMB), 256>>>(proj_w, pWh, pWl, C_EMB);
    wsplit_kernel<<<dim3((C_EMB / 8 + 255) / 256, FFN_DIM), 256>>>(gate_w, gWh, gWl, C_EMB);
    wsplit_kernel<<<dim3((C_EMB / 8 + 255) / 256, FFN_DIM), 256>>>(up_w, uWh, uWl, C_EMB);
    wsplit_kernel<<<dim3((FFN_DIM / 8 + 255) / 256, C_EMB), 256>>>(down_w, dWh, dWl, FFN_DIM);

    // 1. n1 = rmsnorm(x) -> bf16 hi/lo
    rmsnorm_split_kernel<<<T_SEQ, 256>>>(x, norm1_w, n1h, n1l);

    // 2. qkv = n1 @ attn_w^T  (fp32 out)
    tcmm<0><<<dim3(16, QKV_OUT / 128, 1), 256, SMEM>>>(
        n1h, n1l, aWh, aWl, qkv, nullptr, nullptr,
        C_EMB, C_EMB, C_EMB, QKV_OUT, 0, 0, 0, 1, nullptr, 0.f);

    // 3. scaling = relu(n1 @ scale_w^T + scale_b)
    tcmm<1><<<dim3(16, C_EMB / 128, 1), 256, SMEM>>>(
        n1h, n1l, sWh, sWl, scaling, nullptr, nullptr,
        C_EMB, C_EMB, C_EMB, C_EMB, 0, 0, 0, 1, scale_b, 0.f);

    // 4. per-(t,h) mean
    scalet_kernel<<<T_SEQ, 1024>>>(scaling, scale_t);

    // 5. rope + splits
    ropeq_kernel<<<(NHEAD * T_SEQ * 64) / 256, 256>>>(qkv, cosp, sinp, qh, ql);
    ropek_kernel<<<(NKV * T_SEQ * 64) / 256, 256>>>(qkv, cosp, sinp, kh, kl);
    vsplit_kernel<<<(NKV * HDIM * T_SEQ) / 256, 256>>>(qkv, vth, vtl);

    // 6. scores[h] = (Q[h] @ K[g]^T) * sf * scale_t[:,h]
    tcmm<3><<<dim3(16, 16, NHEAD), 256, SMEM>>>(
        qh, ql, kh, kl, scores, nullptr, nullptr,
        HDIM, HDIM, HDIM, T_SEQ,
        (long)T_SEQ * HDIM, (long)T_SEQ * HDIM, (long)T_SEQ * T_SEQ, 4,
        scale_t, sf);

    // 7. softmax (writes P hi/lo bf16 in place)
    softmax_kernel<<<NHEAD * T_SEQ, 256>>>(scores);

    // 8. y[:, h*128:+128] = P[h] @ V[g]  -> bf16 hi/lo planes
    tcmm<4><<<dim3(16, 1, NHEAD), 256, SMEM>>>(
        (const bf16*)scores, (const bf16*)scores + 2048, vth, vtl,
        nullptr, yh, yl,
        T_SEQ, 2 * T_SEQ, T_SEQ, C_EMB,
        (long)T_SEQ * 2 * T_SEQ, (long)HDIM * T_SEQ, (long)HDIM, 4,
        nullptr, 0.f);

    // 9. x2 = x + y @ proj_w^T
    tcmm<2><<<dim3(16, C_EMB / 128, 1), 256, SMEM>>>(
        yh, yl, pWh, pWl, x2, nullptr, nullptr,
        C_EMB, C_EMB, C_EMB, C_EMB, 0, 0, 0, 1, x, 0.f);

    // 10. n2 = rmsnorm(x2)
    rmsnorm_split_kernel<<<T_SEQ, 256>>>(x2, norm2_w, n2h, n2l);

    // 11/12. gate & up
    tcmm<0><<<dim3(16, FFN_DIM / 128, 1), 256, SMEM>>>(
        n2h, n2l, gWh, gWl, gateb, nullptr, nullptr,
        C_EMB, C_EMB, C_EMB, FFN_DIM, 0, 0, 0, 1, nullptr, 0.f);
    tcmm<0><<<dim3(16, FFN_DIM / 128, 1), 256, SMEM>>>(
        n2h, n2l, uWh, uWl, upb, nullptr, nullptr,
        C_EMB, C_EMB, C_EMB, FFN_DIM, 0, 0, 0, 1, nullptr, 0.f);

    // 13. gh/gl = split(silu(gate) * up)
    {
        long n = (long)T_SEQ * FFN_DIM;
        silumul_split_kernel<<<(unsigned)((n / 4 + 255) / 256), 256>>>(gateb, upb, gh, gl, n);
    }

    // 14. out = x2 + (silu*up) @ down_w^T
    tcmm<2><<<dim3(16, C_EMB / 128, 1), 256, SMEM>>>(
        gh, gl, dWh, dWl, out, nullptr, nullptr,
        FFN_DIM, FFN_DIM, FFN_DIM, C_EMB, 0, 0, 0, 1, x2, 0.f);
}